// round 14
// baseline (speedup 1.0000x reference)
#include <cuda_runtime.h>
#include <cuda_bf16.h>
#include <math.h>
#include <stdint.h>

// Problem constants
#define NROWS 16384
#define NE    16384
#define D     256
#define HW    1024
#define CHW   262144

#define NT       128        // number of 128-code tiles
#define MARGIN_M 2e-4f      // margin on m_hat (provable bound ~9.6e-5)

// Output layout (concatenated reference tuple, float32)
#define ZQ_OFF   0ULL
#define LOSS_OFF 4194304ULL
#define PERP_OFF 4194305ULL
#define OH_OFF   4194306ULL
#define OH_ALN   4194308ULL  // first 16B-aligned float index in OH region
#define IDX_OFF  272629762ULL

// Scratch
__device__ float  g_enorm[NE];
__device__ float  g_znorm[NROWS];
__device__ int    g_idx[NROWS];
__device__ int    g_count[NE];
__device__ double g_losspart[128];
__device__ uint4  g_ebf8[NE * 32];              // bf16 codebook, tile-major + swizzled (8 MB)
__device__ float  g_smax[(size_t)NROWS * 1024]; // per-row per-16-code-subtile max(m_hat)
__device__ float  g_tmax[(size_t)NROWS * 128];  // per-row per-128-code-tile max(m_hat)

// ---------------------------------------------------------------------------
// Baseline-PTX helpers (sm_90 features only)
// ---------------------------------------------------------------------------
__device__ __forceinline__ uint32_t smem_to_u32(const void* p) {
    uint32_t a;
    asm("{ .reg .u64 t; cvta.to.shared.u64 t, %1; cvt.u32.u64 %0, t; }" : "=r"(a) : "l"(p));
    return a;
}
#define MBARRIER_INIT(mb, cnt) \
    asm volatile("mbarrier.init.shared.b64 [%0], %1;" :: "r"((uint32_t)(mb)), "r"((uint32_t)(cnt)) : "memory")
#define MBARRIER_EXPECT_TX(mb, bytes) \
    asm volatile("mbarrier.arrive.expect_tx.shared.b64 _, [%0], %1;" :: "r"((uint32_t)(mb)), "r"((uint32_t)(bytes)) : "memory")
#define MBARRIER_WAIT_PARITY(mb, ph) do {                                          \
    uint32_t _m = (uint32_t)(mb); uint32_t _p = (uint32_t)(ph); uint32_t _d;       \
    asm volatile("{\n\t.reg .pred p;\n\t"                                          \
        "mbarrier.try_wait.parity.shared.b64 p, [%1], %2;\n\t"                     \
        "selp.b32 %0, 1, 0, p;\n\t}" : "=r"(_d) : "r"(_m), "r"(_p) : "memory");    \
    if (!_d) {                                                                     \
        asm volatile("{\n\t.reg .pred P1;\n\tWL_%=:\n\t"                           \
            "mbarrier.try_wait.parity.shared.b64 P1, [%0], %1;\n\t"                \
            "@P1 bra.uni WD_%=;\n\tbra.uni WL_%=;\n\tWD_%=:\n\t}"                  \
            :: "r"(_m), "r"(_p) : "memory");                                       \
    } } while (0)

__device__ __forceinline__ void bulk_g2s(uint32_t dst, const void* src, uint32_t bytes, uint32_t mbar) {
    asm volatile("cp.async.bulk.shared::cluster.global.mbarrier::complete_tx::bytes [%0], [%1], %2, [%3];"
                 :: "r"(dst), "l"(src), "r"(bytes), "r"(mbar) : "memory");
}
__device__ __forceinline__ void ldm_x4(uint32_t* r, uint32_t addr) {
    asm volatile("ldmatrix.sync.aligned.m8n8.x4.shared.b16 {%0,%1,%2,%3}, [%4];"
                 : "=r"(r[0]), "=r"(r[1]), "=r"(r[2]), "=r"(r[3]) : "r"(addr));
}
__device__ __forceinline__ void mma16816(float* c, const uint32_t* a, uint32_t b0, uint32_t b1) {
    asm volatile("mma.sync.aligned.m16n8k16.row.col.f32.bf16.bf16.f32 "
                 "{%0,%1,%2,%3}, {%4,%5,%6,%7}, {%8,%9}, {%0,%1,%2,%3};"
                 : "+f"(c[0]), "+f"(c[1]), "+f"(c[2]), "+f"(c[3])
                 : "r"(a[0]), "r"(a[1]), "r"(a[2]), "r"(a[3]), "r"(b0), "r"(b1));
}

// ---------------------------------------------------------------------------
__global__ void k_zero_counts() {
    int i = blockIdx.x * blockDim.x + threadIdx.x;
    if (i < NE) g_count[i] = 0;
}

// ---------------------------------------------------------------------------
// Fused e-prep: exact sequential ||e||^2 + bf16 codebook tile-major swizzled
// ---------------------------------------------------------------------------
__global__ void k_eprep(const float* __restrict__ emb) {
    __shared__ float se[32 * 257];
    int r0 = blockIdx.x * 32;
    int tid = threadIdx.x;
    const float* src = emb + (size_t)r0 * D;
    #pragma unroll
    for (int l = 0; l < 32; l++) {
        int i = l * 256 + tid;
        se[(i >> 8) * 257 + (i & 255)] = src[i];
    }
    __syncthreads();
    #pragma unroll
    for (int l = 0; l < 4; l++) {
        int id = l * 256 + tid;
        int r = id >> 5, c = id & 31;
        int j = r0 + r;
        int tile = j >> 7, n = j & 127;
        const float* s8 = se + r * 257 + c * 8;
        uint32_t w[4];
        #pragma unroll
        for (int q = 0; q < 4; q++) {
            __nv_bfloat16 h0 = __float2bfloat16_rn(s8[q * 2]);
            __nv_bfloat16 h1 = __float2bfloat16_rn(s8[q * 2 + 1]);
            w[q] = (uint32_t)*(unsigned short*)&h0 | ((uint32_t)*(unsigned short*)&h1 << 16);
        }
        g_ebf8[(size_t)tile * 4096 + n * 32 + (c ^ (n & 7))] =
            make_uint4(w[0], w[1], w[2], w[3]);
    }
    if (tid < 32) {
        float s = 0.f;
        const float* row = se + tid * 257;
        for (int k = 0; k < D; k++) s = __fadd_rn(s, __fmul_rn(row[k], row[k]));
        g_enorm[r0 + tid] = s;
    }
}

// ---------------------------------------------------------------------------
// Main bf16 mma.sync GEMM — 512 threads, 16 warps (4x4), bulk-DMA double
// buffer, fused znorm + fused one-hot zero-fill + subtile/tile max outputs.
// ---------------------------------------------------------------------------
#define A_OFF  0
#define B_OFF  65536
#define B_SZ   65536
#define ST_OFF (B_OFF + 2 * B_SZ)           // 196608: stmax[2][128][9] floats
#define MB_OFF (ST_OFF + 2 * 128 * 9 * 4)   // 205824
#define SMEM_BYTES (MB_OFF + 64)            // 205888

__launch_bounds__(512, 1)
__global__ void k_main(const float* __restrict__ z, float* __restrict__ out) {
    extern __shared__ char smem[];
    uint32_t sbase = smem_to_u32(smem);
    float* stmax = (float*)(smem + ST_OFF);
    uint32_t mb0 = sbase + MB_OFF, mb1 = sbase + MB_OFF + 8;

    int tid  = threadIdx.x;
    int lane = tid & 31;
    int wid  = tid >> 5;
    int wm = wid >> 2;      // 0..3
    int wn = wid & 3;       // 0..3
    int row0 = blockIdx.x * 128;
    int b0 = row0 >> 10;
    int hw0 = row0 & 1023;

    if (tid == 0) { MBARRIER_INIT(mb0, 1); MBARRIER_INIT(mb1, 1); }
    __syncthreads();
    if (tid == 0) {
        MBARRIER_EXPECT_TX(mb0, B_SZ);
        bulk_g2s(sbase + B_OFF, g_ebf8, B_SZ, mb0);
        MBARRIER_EXPECT_TX(mb1, B_SZ);
        bulk_g2s(sbase + B_OFF + B_SZ, g_ebf8 + 4096, B_SZ, mb1);
    }
    if (blockIdx.x == 0 && tid == 0) {
        out[OH_OFF] = 0.f; out[OH_OFF + 1] = 0.f;   // unaligned head of OH region
    }

    // ---- Stage A: z -> bf16 smem (swizzled) + exact sequential znorm ----
    if (tid < 128) {
        int m = tid;
        const float* zb = z + (size_t)b0 * CHW + hw0 + m;
        int mx7 = m & 7;
        float s = 0.f;
        #pragma unroll 4
        for (int c = 0; c < 32; c++) {
            float v[8];
            #pragma unroll
            for (int q = 0; q < 8; q++) v[q] = zb[(size_t)(c * 8 + q) * HW];
            #pragma unroll
            for (int q = 0; q < 8; q++) s = __fadd_rn(s, __fmul_rn(v[q], v[q]));
            uint32_t w[4];
            #pragma unroll
            for (int q = 0; q < 4; q++) {
                __nv_bfloat16 h0 = __float2bfloat16_rn(v[q * 2]);
                __nv_bfloat16 h1 = __float2bfloat16_rn(v[q * 2 + 1]);
                w[q] = (uint32_t)*(unsigned short*)&h0 | ((uint32_t)*(unsigned short*)&h1 << 16);
            }
            *(uint4*)(smem + A_OFF + m * 512 + ((c ^ mx7) << 4)) =
                make_uint4(w[0], w[1], w[2], w[3]);
        }
        g_znorm[row0 + m] = s;
    }
    __syncthreads();

    const uint4 zz4 = make_uint4(0u, 0u, 0u, 0u);

    // =========================== GEMM main loop =============================
    #pragma unroll 1
    for (int t = 0; t < NT; t++) {
        int buf = t & 1;
        MBARRIER_WAIT_PARITY(buf ? mb1 : mb0, (t >> 1) & 1);

        // Fused zero-fill: 4096 uint4 = 64 KB of the one-hot region per tile.
        {
            uint4* zdst = (uint4*)(out + OH_ALN) + (((size_t)blockIdx.x) * NT + t) * 4096;
            #pragma unroll
            for (int q = 0; q < 8; q++) zdst[q * 512 + tid] = zz4;
        }

        float acc[2][4][4];
        #pragma unroll
        for (int mt = 0; mt < 2; mt++)
            #pragma unroll
            for (int nt = 0; nt < 4; nt++)
                #pragma unroll
                for (int rr = 0; rr < 4; rr++) acc[mt][nt][rr] = 0.f;

        int rA = wm * 32 + (lane & 15);
        int rB = wn * 32 + (lane & 15);
        int hi = lane >> 4;
        uint32_t bB = sbase + B_OFF + (uint32_t)buf * B_SZ;

        #pragma unroll
        for (int ks = 0; ks < 16; ks++) {
            int chunk = ks * 2 + hi;
            uint32_t ra[2][4], rb[2][4];
            #pragma unroll
            for (int mt = 0; mt < 2; mt++) {
                int r = rA + mt * 16;
                ldm_x4(ra[mt], sbase + A_OFF + (uint32_t)(r * 512 + ((chunk ^ (r & 7)) << 4)));
            }
            #pragma unroll
            for (int np = 0; np < 2; np++) {
                int r = rB + np * 16;
                ldm_x4(rb[np], bB + (uint32_t)(r * 512 + ((chunk ^ (r & 7)) << 4)));
            }
            #pragma unroll
            for (int mt = 0; mt < 2; mt++) {
                mma16816(acc[mt][0], ra[mt], rb[0][0], rb[0][2]);
                mma16816(acc[mt][1], ra[mt], rb[0][1], rb[0][3]);
                mma16816(acc[mt][2], ra[mt], rb[1][0], rb[1][2]);
                mma16816(acc[mt][3], ra[mt], rb[1][1], rb[1][3]);
            }
        }

        // ---- Epilogue: per-(row, 16-code subtile) max of m_hat ----
        float* stm = stmax + buf * (128 * 9);
        #pragma unroll
        for (int mt = 0; mt < 2; mt++) {
            int rl = wm * 32 + mt * 16 + (lane >> 2);
            #pragma unroll
            for (int sb = 0; sb < 2; sb++) {
                float m0 = fmaxf(fmaxf(acc[mt][sb*2][0], acc[mt][sb*2][1]),
                                 fmaxf(acc[mt][sb*2+1][0], acc[mt][sb*2+1][1]));
                float m1 = fmaxf(fmaxf(acc[mt][sb*2][2], acc[mt][sb*2][3]),
                                 fmaxf(acc[mt][sb*2+1][2], acc[mt][sb*2+1][3]));
                m0 = fmaxf(m0, __shfl_xor_sync(0xffffffffu, m0, 1));
                m0 = fmaxf(m0, __shfl_xor_sync(0xffffffffu, m0, 2));
                m1 = fmaxf(m1, __shfl_xor_sync(0xffffffffu, m1, 1));
                m1 = fmaxf(m1, __shfl_xor_sync(0xffffffffu, m1, 2));
                if ((lane & 3) == 0) {
                    stm[rl * 9 + wn * 2 + sb]       = m0;
                    stm[(rl + 8) * 9 + wn * 2 + sb] = m1;
                }
            }
        }
        __syncthreads();
        if (tid < 128) {
            const float* s = stm + tid * 9;
            float4 v0 = make_float4(s[0], s[1], s[2], s[3]);
            float4 v1 = make_float4(s[4], s[5], s[6], s[7]);
            float4* d = (float4*)(g_smax + (size_t)(row0 + tid) * 1024 + t * 8);
            d[0] = v0; d[1] = v1;
            float mx = fmaxf(fmaxf(fmaxf(v0.x, v0.y), fmaxf(v0.z, v0.w)),
                             fmaxf(fmaxf(v1.x, v1.y), fmaxf(v1.z, v1.w)));
            g_tmax[(size_t)(row0 + tid) * 128 + t] = mx;
        }
        if (tid == 0 && t + 2 < NT) {
            uint32_t mb = buf ? mb1 : mb0;
            MBARRIER_EXPECT_TX(mb, B_SZ);
            bulk_g2s(sbase + B_OFF + (uint32_t)buf * B_SZ,
                     g_ebf8 + (size_t)(t + 2) * 4096, B_SZ, mb);
        }
    }
}

// ---------------------------------------------------------------------------
// Exact rescore (hierarchical): 512 CTAs x 256 threads, 32 rows/CTA, warp per
// row (4 rows per warp). Read 128 tile-maxima (512B coalesced), flag tiles
// within MARGIN_M, expand to subtiles via g_smax, exact fp32 chain on the 16
// codes of each flagged subtile.
// ---------------------------------------------------------------------------
#define RS_ROWS 32
#define RS_SMEM (RS_ROWS * 260 * 4)

__global__ void k_rescore(const float* __restrict__ z, const float* __restrict__ emb) {
    extern __shared__ float zs[];            // [32][260]
    __shared__ int tlist[8][16];
    __shared__ int slist[8][32];
    __shared__ int tcnt[8], scnt[8];
    int tid = threadIdx.x;
    int lane = tid & 31;
    int wp = tid >> 5;
    int row0 = blockIdx.x * RS_ROWS;
    int b = row0 >> 10, hw0 = row0 & 1023;
    const float* zsrc = z + (size_t)b * CHW + hw0;

    #pragma unroll 4
    for (int it = 0; it < RS_ROWS; it++) {
        int id = it * 256 + tid;
        int c = id >> 5, h = id & 31;
        zs[h * 260 + c] = zsrc[(size_t)c * HW + h];
    }
    __syncthreads();

    #pragma unroll 1
    for (int rr = 0; rr < 4; rr++) {
        int row = wp * 4 + rr;
        int w = row0 + row;
        if (lane == 0) { tcnt[wp] = 0; scnt[wp] = 0; }
        __syncwarp();

        // ---- level 1: tile maxima (128 floats, coalesced) ----
        float4 tv = ((const float4*)(g_tmax + (size_t)w * 128))[lane];
        float mx = fmaxf(fmaxf(tv.x, tv.y), fmaxf(tv.z, tv.w));
        #pragma unroll
        for (int o = 16; o; o >>= 1) mx = fmaxf(mx, __shfl_xor_sync(0xffffffffu, mx, o));
        float thr = mx - MARGIN_M;

        if (tv.x > thr) { int p = atomicAdd(&tcnt[wp], 1); if (p < 16) tlist[wp][p] = lane * 4; }
        if (tv.y > thr) { int p = atomicAdd(&tcnt[wp], 1); if (p < 16) tlist[wp][p] = lane * 4 + 1; }
        if (tv.z > thr) { int p = atomicAdd(&tcnt[wp], 1); if (p < 16) tlist[wp][p] = lane * 4 + 2; }
        if (tv.w > thr) { int p = atomicAdd(&tcnt[wp], 1); if (p < 16) tlist[wp][p] = lane * 4 + 3; }
        __syncwarp();
        int ntl = tcnt[wp];
        bool overflow = (ntl > 16);

        // ---- level 2: subtile maxima of flagged tiles ----
        if (!overflow) {
            for (int ti = 0; ti < ntl; ti++) {
                int T = tlist[wp][ti];
                float sv = (lane < 8) ? g_smax[(size_t)w * 1024 + T * 8 + lane] : -INFINITY;
                if (sv > thr) {
                    int p = atomicAdd(&scnt[wp], 1);
                    if (p < 32) slist[wp][p] = T * 8 + lane;
                }
            }
            __syncwarp();
            if (scnt[wp] > 32) overflow = true;
        }
        int ns = scnt[wp];

        float Sz = g_znorm[w];
        const float4* zrow4 = (const float4*)(zs + row * 260);
        float bestd = INFINITY; int besti = 0x7fffffff;

        if (!overflow) {
            for (int base = 0; base < ns; base += 2) {
                int li = base + (lane >> 4);
                float dd = INFINITY; int code = 0x7fffffff;
                if (li < ns) {
                    code = slist[wp][li] * 16 + (lane & 15);
                    const float4* er = (const float4*)(emb + (size_t)code * D);
                    float a = 0.f;
                    #pragma unroll 16
                    for (int q = 0; q < 64; q++) {
                        float4 ev = er[q];
                        float4 zv = zrow4[q];
                        a = fmaf(zv.x, ev.x, a);
                        a = fmaf(zv.y, ev.y, a);
                        a = fmaf(zv.z, ev.z, a);
                        a = fmaf(zv.w, ev.w, a);
                    }
                    dd = __fadd_rn(__fadd_rn(Sz, g_enorm[code]), __fmul_rn(-2.0f, a));
                }
                if (dd < bestd || (dd == bestd && code < besti)) { bestd = dd; besti = code; }
            }
        } else {
            // overflow (effectively impossible): full subtile scan
            const float* sm = g_smax + (size_t)w * 1024;
            for (int sb = 0; sb < 1024; sb += 2) {
                int s = sb + (lane >> 4);
                float dd = INFINITY; int code = 0x7fffffff;
                if (sm[s] > thr) {
                    code = s * 16 + (lane & 15);
                    const float4* er = (const float4*)(emb + (size_t)code * D);
                    float a = 0.f;
                    for (int q = 0; q < 64; q++) {
                        float4 ev = er[q];
                        float4 zv = zrow4[q];
                        a = fmaf(zv.x, ev.x, a);
                        a = fmaf(zv.y, ev.y, a);
                        a = fmaf(zv.z, ev.z, a);
                        a = fmaf(zv.w, ev.w, a);
                    }
                    dd = __fadd_rn(__fadd_rn(Sz, g_enorm[code]), __fmul_rn(-2.0f, a));
                }
                if (dd < bestd || (dd == bestd && code < besti)) { bestd = dd; besti = code; }
            }
        }
        #pragma unroll
        for (int o = 16; o; o >>= 1) {
            float vo = __shfl_xor_sync(0xffffffffu, bestd, o);
            int io = __shfl_xor_sync(0xffffffffu, besti, o);
            if (vo < bestd || (vo == bestd && io < besti)) { bestd = vo; besti = io; }
        }
        if (lane == 0) g_idx[w] = besti;
    }
}

// ---------------------------------------------------------------------------
// zq + straight-through + loss partials: 128 CTAs x 256 threads, 128 rows/CTA.
// ---------------------------------------------------------------------------
#define ZQ_SMEM (128 * 260 * 4)

__global__ void k_zq_loss(const float* __restrict__ z, const float* __restrict__ emb,
                          float* __restrict__ out) {
    extern __shared__ float zs[];            // [128][260]
    __shared__ double lsum[8];
    int tid = threadIdx.x;
    int lane = tid & 31;
    int wp = tid >> 5;
    int row0 = blockIdx.x * 128;
    int b = row0 >> 10, hw0 = row0 & 1023;
    const float* zsrc = z + (size_t)b * CHW + hw0;

    #pragma unroll 4
    for (int it = 0; it < 128; it++) {
        int id = it * 256 + tid;
        int c = id >> 7, h = id & 127;
        zs[h * 260 + c] = zsrc[(size_t)c * HW + h];
    }
    __syncthreads();

    double acc = 0.0;
    #pragma unroll 1
    for (int rr = 0; rr < 16; rr++) {
        int row = wp * 16 + rr;
        int idx = g_idx[row0 + row];
        const float4* er = (const float4*)(emb + (size_t)idx * D);
        float4* zrow = (float4*)(zs + row * 260);
        #pragma unroll
        for (int s = 0; s < 2; s++) {
            int c4 = lane + s * 32;
            float4 e4 = er[c4];
            float4 z4 = zrow[c4];
            float d0 = __fadd_rn(e4.x, -z4.x);
            float d1 = __fadd_rn(e4.y, -z4.y);
            float d2 = __fadd_rn(e4.z, -z4.z);
            float d3 = __fadd_rn(e4.w, -z4.w);
            zrow[c4] = make_float4(__fadd_rn(z4.x, d0), __fadd_rn(z4.y, d1),
                                   __fadd_rn(z4.z, d2), __fadd_rn(z4.w, d3));
            acc += (double)d0 * d0 + (double)d1 * d1
                 + (double)d2 * d2 + (double)d3 * d3;
        }
    }
    #pragma unroll
    for (int o = 16; o; o >>= 1) acc += __shfl_xor_sync(0xffffffffu, acc, o);
    if (lane == 0) lsum[wp] = acc;
    __syncthreads();
    if (tid == 0) {
        double s = 0.0;
        #pragma unroll
        for (int i = 0; i < 8; i++) s += lsum[i];
        g_losspart[blockIdx.x] = s;
    }

    float* odst = out + ZQ_OFF + (size_t)b * CHW + hw0;
    #pragma unroll 4
    for (int it = 0; it < 128; it++) {
        int id = it * 256 + tid;
        int c = id >> 7, h = id & 127;
        odst[(size_t)c * HW + h] = zs[h * 260 + c];
    }
}

__global__ void k_loss_final(float* __restrict__ out) {
    __shared__ double sd[128];
    int t = threadIdx.x;
    sd[t] = g_losspart[t];
    __syncthreads();
    #pragma unroll
    for (int st = 64; st > 0; st >>= 1) {
        if (t < st) sd[t] += sd[t + st];
        __syncthreads();
    }
    if (t == 0) {
        float m = (float)(sd[0] / 4194304.0);
        out[LOSS_OFF] = __fadd_rn(m, __fmul_rn(0.25f, m));
    }
}

// ---------------------------------------------------------------------------
__global__ void k_finalize(float* __restrict__ out) {
    int r = blockIdx.x * blockDim.x + threadIdx.x;
    if (r >= NROWS) return;
    int idx = g_idx[r];
    out[IDX_OFF + r] = (float)idx;
    out[OH_OFF + (size_t)r * NE + idx] = 1.0f;
    atomicAdd(&g_count[idx], 1);
}

__global__ void k_perp(float* __restrict__ out) {
    __shared__ double sd[1024];
    double s = 0.0;
    for (int j = threadIdx.x; j < NE; j += 1024) {
        float p = (float)g_count[j] * (1.0f / 16384.0f);
        double pd = (double)p;
        s += pd * log(pd + 1e-10);
    }
    sd[threadIdx.x] = s;
    __syncthreads();
    #pragma unroll
    for (int st = 512; st > 0; st >>= 1) {
        if (threadIdx.x < st) sd[threadIdx.x] += sd[threadIdx.x + st];
        __syncthreads();
    }
    if (threadIdx.x == 0) out[PERP_OFF] = (float)exp(-sd[0]);
}

// ---------------------------------------------------------------------------
extern "C" void kernel_launch(void* const* d_in, const int* in_sizes, int n_in,
                              void* d_out, int out_size) {
    const float* z   = (const float*)d_in[0];
    const float* emb = (const float*)d_in[1];
    float* out = (float*)d_out;

    static int configured = 0;
    if (!configured) {
        cudaFuncSetAttribute(k_main, cudaFuncAttributeMaxDynamicSharedMemorySize, SMEM_BYTES);
        cudaFuncSetAttribute(k_rescore, cudaFuncAttributeMaxDynamicSharedMemorySize, RS_SMEM);
        cudaFuncSetAttribute(k_zq_loss, cudaFuncAttributeMaxDynamicSharedMemorySize, ZQ_SMEM);
        configured = 1;
    }

    k_zero_counts<<<64, 256>>>();
    k_eprep<<<NE / 32, 256>>>(emb);
    k_main<<<128, 512, SMEM_BYTES>>>(z, out);          // GEMM + zero-fill + maxima
    k_rescore<<<NROWS / RS_ROWS, 256, RS_SMEM>>>(z, emb);
    k_zq_loss<<<128, 256, ZQ_SMEM>>>(z, emb, out);
    k_loss_final<<<1, 128>>>(out);
    k_finalize<<<NROWS / 256, 256>>>(out);
    k_perp<<<1, 1024>>>(out);
}